// round 10
// baseline (speedup 1.0000x reference)
#include <cuda_runtime.h>
#include <cuda_bf16.h>
#include <cstdint>

#define Bb 8
#define Ss 2048
#define Hh 3584
#define Ee 8
#define Rr 16
#define Kk 2
#define Jj 32
#define SCALING 2.0f

#define NSPLIT 4
#define HSPLIT (Hh / NSPLIT)     // 896
#define KC 32
#define NCHUNK (HSPLIT / KC)     // 28
#define NTOK (Bb * Ss)           // 16384

// Scratch (static device globals — no allocation). 16B-aligned (float4 access).
__device__ __align__(16) float g_Ac [(size_t)Bb * Hh * Jj];          // [b][h][j], w*scaling folded
__device__ __align__(16) float g_Bc [(size_t)Bb * Jj * Hh];          // [b][j][h]
__device__ __align__(16) float g_lowp[(size_t)NSPLIT * NTOK * Jj];   // partials [split][tok][j]
__device__ __align__(16) float g_low [(size_t)NTOK * Jj];            // [tok][j]

union U2 { unsigned long long u; float2 f; };

__device__ __forceinline__ unsigned long long fma2(unsigned long long a,
                                                   unsigned long long b,
                                                   unsigned long long c) {
    unsigned long long d;
    asm("fma.rn.f32x2 %0, %1, %2, %3;" : "=l"(d) : "l"(a), "l"(b), "l"(c));
    return d;
}
__device__ __forceinline__ unsigned long long dup2(float v) {
    unsigned long long d;
    asm("mov.b64 %0, {%1, %1};" : "=l"(d) : "f"(v));
    return d;
}

// ---------------------------------------------------------------------------
// prep: Ac [b][h][j] (j-fast coalesced) and Bc [b][j][h].
// grid (Bb, Hh/128), 128 threads (224 CTAs: latency-bound before at 112).
// ---------------------------------------------------------------------------
__global__ void __launch_bounds__(128) prep_kernel(const float* __restrict__ A,
                                                   const float* __restrict__ Bm,
                                                   const float* __restrict__ w,
                                                   const int*   __restrict__ idx)
{
    __shared__ int   es[Jj];
    __shared__ float scs[Jj];
    int b = blockIdx.x;
    int hb = blockIdx.y * 128;
    int tid = threadIdx.x;
    if (tid < Jj) {
        int k = tid >> 4;
        es[tid]  = idx[b * Kk + k];
        scs[tid] = w[b * Kk + k] * SCALING;
    }
    __syncthreads();

#pragma unroll 8
    for (int t = tid; t < 128 * Jj; t += 128) {
        int h = hb + (t >> 5);
        int j = t & 31;
        int r = j & 15;
        g_Ac[((size_t)b * Hh + h) * Jj + j] =
            A[((size_t)(es[j] * Rr + r)) * Hh + h] * scs[j];
    }
#pragma unroll 8
    for (int t = tid; t < 128 * Jj; t += 128) {
        int j = t >> 7;
        int h = hb + (t & 127);
        int r = j & 15;
        g_Bc[((size_t)b * Jj + j) * Hh + h] =
            Bm[((size_t)es[j] * Hh + h) * Rr + r];
    }
}

// ---------------------------------------------------------------------------
// low: partial low over a k-split. grid (256 tok-tiles of 64, NSPLIT), 128 thr.
// (Measured version from the 211.7us run, unchanged.)
// ---------------------------------------------------------------------------
__global__ void __launch_bounds__(128) low_kernel(const float* __restrict__ x)
{
    __shared__ __align__(16) float xsm[64][36];    // [tok][k]; row 144B
    __shared__ __align__(16) float asm_[KC][Jj];   // [k][j]; row 128B

    int tid = threadIdx.x;
    int jg = tid & 7;          // 8 j-groups of 4 (2 j-pairs)
    int sg = tid >> 3;         // 16 token-groups of 4
    int tokbase = blockIdx.x * 64;
    int split = blockIdx.y;
    int b = tokbase >> 11;
    int k0base = split * HSPLIT;

    unsigned long long acc[4][2];
#pragma unroll
    for (int c = 0; c < 4; c++) { acc[c][0] = 0ULL; acc[c][1] = 0ULL; }

    const float* xb = x + (size_t)tokbase * Hh + k0base;
    const float4* acb = (const float4*)(g_Ac + ((size_t)b * Hh + k0base) * Jj);

    float4 px[4], pa[2];
#pragma unroll
    for (int i = 0; i < 4; i++) {
        int f4 = tid + 128 * i;
        int tok = f4 >> 3, kq = f4 & 7;
        px[i] = *(const float4*)&xb[(size_t)tok * Hh + kq * 4];
    }
#pragma unroll
    for (int i = 0; i < 2; i++) pa[i] = acb[tid + 128 * i];

    for (int g = 0; g < NCHUNK; g++) {
        __syncthreads();
#pragma unroll
        for (int i = 0; i < 4; i++) {
            int f4 = tid + 128 * i;
            int tok = f4 >> 3, kq = f4 & 7;
            *(float4*)&xsm[tok][kq * 4] = px[i];
        }
#pragma unroll
        for (int i = 0; i < 2; i++)
            ((float4*)asm_)[tid + 128 * i] = pa[i];
        __syncthreads();

        if (g + 1 < NCHUNK) {
            int k0 = (g + 1) * KC;
#pragma unroll
            for (int i = 0; i < 4; i++) {
                int f4 = tid + 128 * i;
                int tok = f4 >> 3, kq = f4 & 7;
                px[i] = *(const float4*)&xb[(size_t)tok * Hh + k0 + kq * 4];
            }
#pragma unroll
            for (int i = 0; i < 2; i++)
                pa[i] = acb[(size_t)k0 * 8 + tid + 128 * i];
        }

#pragma unroll 2
        for (int kk4 = 0; kk4 < KC / 4; kk4++) {
            float4 xq[4];
#pragma unroll
            for (int c = 0; c < 4; c++)
                xq[c] = *(const float4*)&xsm[sg * 4 + c][kk4 * 4];
#pragma unroll
            for (int kl = 0; kl < 4; kl++) {
                int kk = kk4 * 4 + kl;
                ulonglong2 av = *(const ulonglong2*)&asm_[kk][jg * 4];
#pragma unroll
                for (int c = 0; c < 4; c++) {
                    float xv = (kl == 0) ? xq[c].x : (kl == 1) ? xq[c].y
                             : (kl == 2) ? xq[c].z : xq[c].w;
                    unsigned long long xd = dup2(xv);
                    acc[c][0] = fma2(xd, av.x, acc[c][0]);
                    acc[c][1] = fma2(xd, av.y, acc[c][1]);
                }
            }
        }
    }

    float* lp = g_lowp + (size_t)split * NTOK * Jj;
#pragma unroll
    for (int c = 0; c < 4; c++) {
        int tok = tokbase + sg * 4 + c;
#pragma unroll
        for (int q = 0; q < 2; q++) {
            U2 u; u.u = acc[c][q];
            *(float2*)&lp[(size_t)tok * Jj + jg * 4 + q * 2] = u.f;
        }
    }
}

// ---------------------------------------------------------------------------
// reduce: sum the NSPLIT partials. grid 256, 256 threads, 8 elems/thread.
// ---------------------------------------------------------------------------
__global__ void __launch_bounds__(256) reduce_kernel()
{
    int base = blockIdx.x * 2048;
#pragma unroll
    for (int r = 0; r < 8; r++) {
        int i = base + r * 256 + threadIdx.x;
        g_low[i] = g_lowp[i]
                 + g_lowp[(size_t)NTOK * Jj + i]
                 + g_lowp[(size_t)2 * NTOK * Jj + i]
                 + g_lowp[(size_t)3 * NTOK * Jj + i];
    }
}

// ---------------------------------------------------------------------------
// out v4: crossbar-optimized. grid (NTOK/64, Hh/64), 128 threads.
// Warp = 16 lanes x 4h (64-h span, bv 256B = 2 wf/j) x 2 token-groups x 8 tok.
// Single pass: thread = 4 h x 8 tokens (acc 16 u64 = 32 regs).
// Per warp per j: 2 bv wf + 2 lq wf = 4 wf per 32 FMA2-cycles (50% crossbar).
// ---------------------------------------------------------------------------
#define HT 64
#define TT 64

__global__ void __launch_bounds__(128, 8) out_kernel(const float* __restrict__ base,
                                                     float* __restrict__ out)
{
    __shared__ __align__(16) float sB[Jj][HT];        // 8 KB
    __shared__ __align__(16) float sLowF[Jj][68];     // [j][tok]; 8.5 KB

    int tid = threadIdx.x;
    int h0 = blockIdx.y * HT;
    int tok0 = blockIdx.x * TT;
    int b = tok0 >> 11;

    // sB: 32 j x 64 h = 512 float4
    const float* bc = g_Bc + (size_t)b * Jj * Hh + h0;
#pragma unroll
    for (int i = 0; i < 4; i++) {
        int f4 = tid + 128 * i;
        int j = f4 >> 4;
        int hq4 = f4 & 15;
        *(float4*)&sB[j][hq4 * 4] = *(const float4*)&bc[(size_t)j * Hh + hq4 * 4];
    }
    // sLow: 64 tok x 32 j (coalesced j-fast LDG, [j][tok] STS)
#pragma unroll
    for (int i = 0; i < 4; i++) {
        int iv = tid + 128 * i;
        int j = iv & 31;
        int tg4 = iv >> 5;
        float4 v;
        v.x = g_low[(size_t)(tok0 + tg4 * 4 + 0) * Jj + j];
        v.y = g_low[(size_t)(tok0 + tg4 * 4 + 1) * Jj + j];
        v.z = g_low[(size_t)(tok0 + tg4 * 4 + 2) * Jj + j];
        v.w = g_low[(size_t)(tok0 + tg4 * 4 + 3) * Jj + j];
        *(float4*)&sLowF[j][tg4 * 4] = v;
    }
    __syncthreads();

    int lane = tid & 31;
    int wid  = tid >> 5;
    int hsub = lane & 15;            // 16 h-groups of 4 -> warp spans 64 h
    int tg   = lane >> 4;            // 2 token-groups per warp
    int wtok = wid * 16 + tg * 8;    // thread's 8-token base (0..56)

    unsigned long long acc[4][4];    // [token-pair][h scalar]
#pragma unroll
    for (int q = 0; q < 4; q++)
#pragma unroll
        for (int hh = 0; hh < 4; hh++) acc[q][hh] = 0ULL;

#pragma unroll 8
    for (int j = 0; j < Jj; j++) {
        float4 bv = *(const float4*)&sB[j][hsub * 4];
        unsigned long long d0 = dup2(bv.x), d1 = dup2(bv.y),
                           d2 = dup2(bv.z), d3 = dup2(bv.w);
#pragma unroll
        for (int m = 0; m < 2; m++) {
            ulonglong2 lq = *(const ulonglong2*)&sLowF[j][wtok + m * 4];
            acc[2*m+0][0] = fma2(lq.x, d0, acc[2*m+0][0]);
            acc[2*m+0][1] = fma2(lq.x, d1, acc[2*m+0][1]);
            acc[2*m+0][2] = fma2(lq.x, d2, acc[2*m+0][2]);
            acc[2*m+0][3] = fma2(lq.x, d3, acc[2*m+0][3]);
            acc[2*m+1][0] = fma2(lq.y, d0, acc[2*m+1][0]);
            acc[2*m+1][1] = fma2(lq.y, d1, acc[2*m+1][1]);
            acc[2*m+1][2] = fma2(lq.y, d2, acc[2*m+1][2]);
            acc[2*m+1][3] = fma2(lq.y, d3, acc[2*m+1][3]);
        }
    }

#pragma unroll
    for (int t = 0; t < 8; t++) {
        int q = t >> 1;
        size_t gi = (size_t)(tok0 + wtok + t) * Hh + h0 + hsub * 4;
        float4 bs = *(const float4*)&base[gi];
        U2 a0, a1, a2, a3;
        a0.u = acc[q][0]; a1.u = acc[q][1]; a2.u = acc[q][2]; a3.u = acc[q][3];
        float4 o;
        if ((t & 1) == 0)
            o = make_float4(bs.x + a0.f.x, bs.y + a1.f.x,
                            bs.z + a2.f.x, bs.w + a3.f.x);
        else
            o = make_float4(bs.x + a0.f.y, bs.y + a1.f.y,
                            bs.z + a2.f.y, bs.w + a3.f.y);
        *(float4*)&out[gi] = o;
    }
}

// ---------------------------------------------------------------------------
extern "C" void kernel_launch(void* const* d_in, const int* in_sizes, int n_in,
                              void* d_out, int out_size)
{
    const float* x    = (const float*)d_in[0];
    const float* base = (const float*)d_in[1];
    const float* lA   = (const float*)d_in[2];
    const float* lB   = (const float*)d_in[3];
    const float* w    = (const float*)d_in[4];
    const int*   idx  = (const int*)  d_in[5];
    float* out = (float*)d_out;

    prep_kernel<<<dim3(Bb, Hh / 128), 128>>>(lA, lB, w, idx);
    low_kernel<<<dim3(NTOK / 64, NSPLIT), 128>>>(x);
    reduce_kernel<<<256, 256>>>();
    out_kernel<<<dim3(NTOK / TT, Hh / HT), 128>>>(base, out);
}

// round 11
// speedup vs baseline: 1.0292x; 1.0292x over previous
#include <cuda_runtime.h>
#include <cuda_bf16.h>
#include <cstdint>

#define Bb 8
#define Ss 2048
#define Hh 3584
#define Ee 8
#define Rr 16
#define Kk 2
#define Jj 32
#define SCALING 2.0f

#define NSPLIT 4
#define HSPLIT (Hh / NSPLIT)     // 896
#define KC 32
#define NCHUNK (HSPLIT / KC)     // 28
#define NTOK (Bb * Ss)           // 16384

// Scratch (static device globals — no allocation). 16B-aligned (float4 access).
__device__ __align__(16) float g_Ac [(size_t)Bb * Hh * Jj];          // [b][h][j], w*scaling folded
__device__ __align__(16) float g_Bc [(size_t)Bb * Jj * Hh];          // [b][j][h]
__device__ __align__(16) float g_lowp[(size_t)NSPLIT * NTOK * Jj];   // partials [split][tok][j]
__device__ __align__(16) float g_low [(size_t)NTOK * Jj];            // [tok][j]

union U2 { unsigned long long u; float2 f; };

__device__ __forceinline__ unsigned long long fma2(unsigned long long a,
                                                   unsigned long long b,
                                                   unsigned long long c) {
    unsigned long long d;
    asm("fma.rn.f32x2 %0, %1, %2, %3;" : "=l"(d) : "l"(a), "l"(b), "l"(c));
    return d;
}
__device__ __forceinline__ unsigned long long dup2(float v) {
    unsigned long long d;
    asm("mov.b64 %0, {%1, %1};" : "=l"(d) : "f"(v));
    return d;
}

// ---------------------------------------------------------------------------
// prep: Ac [b][h][j] (j-fast coalesced) and Bc [b][j][h].
// grid (Bb, Hh/128), 128 threads.  (R9-measured version, unchanged.)
// ---------------------------------------------------------------------------
__global__ void __launch_bounds__(128) prep_kernel(const float* __restrict__ A,
                                                   const float* __restrict__ Bm,
                                                   const float* __restrict__ w,
                                                   const int*   __restrict__ idx)
{
    __shared__ int   es[Jj];
    __shared__ float scs[Jj];
    int b = blockIdx.x;
    int hb = blockIdx.y * 128;
    int tid = threadIdx.x;
    if (tid < Jj) {
        int k = tid >> 4;
        es[tid]  = idx[b * Kk + k];
        scs[tid] = w[b * Kk + k] * SCALING;
    }
    __syncthreads();

#pragma unroll 8
    for (int t = tid; t < 128 * Jj; t += 128) {
        int h = hb + (t >> 5);
        int j = t & 31;
        int r = j & 15;
        g_Ac[((size_t)b * Hh + h) * Jj + j] =
            A[((size_t)(es[j] * Rr + r)) * Hh + h] * scs[j];
    }
#pragma unroll 8
    for (int t = tid; t < 128 * Jj; t += 128) {
        int j = t >> 7;
        int h = hb + (t & 127);
        int r = j & 15;
        g_Bc[((size_t)b * Jj + j) * Hh + h] =
            Bm[((size_t)es[j] * Hh + h) * Rr + r];
    }
}

// ---------------------------------------------------------------------------
// low: partial low over a k-split. grid (256 tok-tiles of 64, NSPLIT), 128 thr.
// (R9-measured version, unchanged.)
// ---------------------------------------------------------------------------
__global__ void __launch_bounds__(128) low_kernel(const float* __restrict__ x)
{
    __shared__ __align__(16) float xsm[64][36];    // [tok][k]; row 144B
    __shared__ __align__(16) float asm_[KC][Jj];   // [k][j]; row 128B

    int tid = threadIdx.x;
    int jg = tid & 7;          // 8 j-groups of 4 (2 j-pairs)
    int sg = tid >> 3;         // 16 token-groups of 4
    int tokbase = blockIdx.x * 64;
    int split = blockIdx.y;
    int b = tokbase >> 11;
    int k0base = split * HSPLIT;

    unsigned long long acc[4][2];
#pragma unroll
    for (int c = 0; c < 4; c++) { acc[c][0] = 0ULL; acc[c][1] = 0ULL; }

    const float* xb = x + (size_t)tokbase * Hh + k0base;
    const float4* acb = (const float4*)(g_Ac + ((size_t)b * Hh + k0base) * Jj);

    float4 px[4], pa[2];
#pragma unroll
    for (int i = 0; i < 4; i++) {
        int f4 = tid + 128 * i;
        int tok = f4 >> 3, kq = f4 & 7;
        px[i] = *(const float4*)&xb[(size_t)tok * Hh + kq * 4];
    }
#pragma unroll
    for (int i = 0; i < 2; i++) pa[i] = acb[tid + 128 * i];

    for (int g = 0; g < NCHUNK; g++) {
        __syncthreads();
#pragma unroll
        for (int i = 0; i < 4; i++) {
            int f4 = tid + 128 * i;
            int tok = f4 >> 3, kq = f4 & 7;
            *(float4*)&xsm[tok][kq * 4] = px[i];
        }
#pragma unroll
        for (int i = 0; i < 2; i++)
            ((float4*)asm_)[tid + 128 * i] = pa[i];
        __syncthreads();

        if (g + 1 < NCHUNK) {
            int k0 = (g + 1) * KC;
#pragma unroll
            for (int i = 0; i < 4; i++) {
                int f4 = tid + 128 * i;
                int tok = f4 >> 3, kq = f4 & 7;
                px[i] = *(const float4*)&xb[(size_t)tok * Hh + k0 + kq * 4];
            }
#pragma unroll
            for (int i = 0; i < 2; i++)
                pa[i] = acb[(size_t)k0 * 8 + tid + 128 * i];
        }

#pragma unroll 2
        for (int kk4 = 0; kk4 < KC / 4; kk4++) {
            float4 xq[4];
#pragma unroll
            for (int c = 0; c < 4; c++)
                xq[c] = *(const float4*)&xsm[sg * 4 + c][kk4 * 4];
#pragma unroll
            for (int kl = 0; kl < 4; kl++) {
                int kk = kk4 * 4 + kl;
                ulonglong2 av = *(const ulonglong2*)&asm_[kk][jg * 4];
#pragma unroll
                for (int c = 0; c < 4; c++) {
                    float xv = (kl == 0) ? xq[c].x : (kl == 1) ? xq[c].y
                             : (kl == 2) ? xq[c].z : xq[c].w;
                    unsigned long long xd = dup2(xv);
                    acc[c][0] = fma2(xd, av.x, acc[c][0]);
                    acc[c][1] = fma2(xd, av.y, acc[c][1]);
                }
            }
        }
    }

    float* lp = g_lowp + (size_t)split * NTOK * Jj;
#pragma unroll
    for (int c = 0; c < 4; c++) {
        int tok = tokbase + sg * 4 + c;
#pragma unroll
        for (int q = 0; q < 2; q++) {
            U2 u; u.u = acc[c][q];
            *(float2*)&lp[(size_t)tok * Jj + jg * 4 + q * 2] = u.f;
        }
    }
}

// ---------------------------------------------------------------------------
// reduce: sum the NSPLIT partials. grid 256, 256 threads, 8 elems/thread.
// ---------------------------------------------------------------------------
__global__ void __launch_bounds__(256) reduce_kernel()
{
    int base = blockIdx.x * 2048;
#pragma unroll
    for (int r = 0; r < 8; r++) {
        int i = base + r * 256 + threadIdx.x;
        g_low[i] = g_lowp[i]
                 + g_lowp[(size_t)NTOK * Jj + i]
                 + g_lowp[(size_t)2 * NTOK * Jj + i]
                 + g_lowp[(size_t)3 * NTOK * Jj + i];
    }
}

// ---------------------------------------------------------------------------
// out v6: warp-slab shape for minimal LDS wavefronts.
// grid (NTOK/64, Hh/128), 128 threads. Warp = 8 h-groups x 4 token-quads:
// warp owns a 32-h x 64-tok slab. Per warp per j: bv 128B contiguous (1 wf,
// broadcast-dedup) + 4 lq loads of 64B contiguous (1 wf each) = 5 wf for
// 32 fma2/thread (was 6 wf/16 with 8x bv duplication). Single pass.
// Thread tokens = 4 quads strided 16 (tq*4 + 16s) -> no 128B bank aliasing.
// ---------------------------------------------------------------------------
#define HT 128
#define TT 64

__global__ void __launch_bounds__(128, 5) out_kernel(const float* __restrict__ base,
                                                     float* __restrict__ out)
{
    __shared__ __align__(16) float sB[Jj][HT];        // 16 KB
    __shared__ __align__(16) float sLowF[Jj][68];     // [j][tok]; 8.5 KB

    int tid = threadIdx.x;
    int h0 = blockIdx.y * HT;
    int tok0 = blockIdx.x * TT;
    int b = tok0 >> 11;

    const float* bc = g_Bc + (size_t)b * Jj * Hh + h0;
#pragma unroll
    for (int i = 0; i < 8; i++) {             // 32*128 floats = 1024 float4
        int f4 = tid + 128 * i;
        int j = f4 >> 5;
        int hq4 = f4 & 31;
        *(float4*)&sB[j][hq4 * 4] = *(const float4*)&bc[(size_t)j * Hh + hq4 * 4];
    }
#pragma unroll
    for (int i = 0; i < 4; i++) {
        int iv = tid + 128 * i;
        int j = iv & 31;
        int tg4 = iv >> 5;
        float4 v;
        v.x = g_low[(size_t)(tok0 + tg4 * 4 + 0) * Jj + j];
        v.y = g_low[(size_t)(tok0 + tg4 * 4 + 1) * Jj + j];
        v.z = g_low[(size_t)(tok0 + tg4 * 4 + 2) * Jj + j];
        v.w = g_low[(size_t)(tok0 + tg4 * 4 + 3) * Jj + j];
        *(float4*)&sLowF[j][tg4 * 4] = v;
    }
    __syncthreads();

    int lane = tid & 31;
    int wid  = tid >> 5;
    int hh   = lane & 7;             // 8 h-groups of 4 -> warp h-span 32
    int tq   = lane >> 3;            // 4 token-quads
    int hbase = wid * 32 + hh * 4;   // h offset within tile [0,128)

    unsigned long long acc[8][4];    // [2s+p][h scalar]; 16 tokens/thread
#pragma unroll
    for (int q = 0; q < 8; q++)
#pragma unroll
        for (int x4 = 0; x4 < 4; x4++) acc[q][x4] = 0ULL;

#pragma unroll 8
    for (int j = 0; j < Jj; j++) {
        float4 bv = *(const float4*)&sB[j][hbase];
        unsigned long long d0 = dup2(bv.x), d1 = dup2(bv.y),
                           d2 = dup2(bv.z), d3 = dup2(bv.w);
#pragma unroll
        for (int s = 0; s < 4; s++) {
            ulonglong2 lq = *(const ulonglong2*)&sLowF[j][tq * 4 + 16 * s];
            acc[2*s+0][0] = fma2(lq.x, d0, acc[2*s+0][0]);
            acc[2*s+0][1] = fma2(lq.x, d1, acc[2*s+0][1]);
            acc[2*s+0][2] = fma2(lq.x, d2, acc[2*s+0][2]);
            acc[2*s+0][3] = fma2(lq.x, d3, acc[2*s+0][3]);
            acc[2*s+1][0] = fma2(lq.y, d0, acc[2*s+1][0]);
            acc[2*s+1][1] = fma2(lq.y, d1, acc[2*s+1][1]);
            acc[2*s+1][2] = fma2(lq.y, d2, acc[2*s+1][2]);
            acc[2*s+1][3] = fma2(lq.y, d3, acc[2*s+1][3]);
        }
    }

#pragma unroll
    for (int s = 0; s < 4; s++) {
#pragma unroll
        for (int t = 0; t < 4; t++) {
            int q = 2 * s + (t >> 1);
            size_t gi = (size_t)(tok0 + tq * 4 + 16 * s + t) * Hh + h0 + hbase;
            float4 bs = *(const float4*)&base[gi];
            U2 a0, a1, a2, a3;
            a0.u = acc[q][0]; a1.u = acc[q][1]; a2.u = acc[q][2]; a3.u = acc[q][3];
            float4 o;
            if ((t & 1) == 0)
                o = make_float4(bs.x + a0.f.x, bs.y + a1.f.x,
                                bs.z + a2.f.x, bs.w + a3.f.x);
            else
                o = make_float4(bs.x + a0.f.y, bs.y + a1.f.y,
                                bs.z + a2.f.y, bs.w + a3.f.y);
            *(float4*)&out[gi] = o;
        }
    }
}

// ---------------------------------------------------------------------------
extern "C" void kernel_launch(void* const* d_in, const int* in_sizes, int n_in,
                              void* d_out, int out_size)
{
    const float* x    = (const float*)d_in[0];
    const float* base = (const float*)d_in[1];
    const float* lA   = (const float*)d_in[2];
    const float* lB   = (const float*)d_in[3];
    const float* w    = (const float*)d_in[4];
    const int*   idx  = (const int*)  d_in[5];
    float* out = (float*)d_out;

    prep_kernel<<<dim3(Bb, Hh / 128), 128>>>(lA, lB, w, idx);
    low_kernel<<<dim3(NTOK / 64, NSPLIT), 128>>>(x);
    reduce_kernel<<<256, 256>>>();
    out_kernel<<<dim3(NTOK / TT, Hh / HT), 128>>>(base, out);
}

// round 12
// speedup vs baseline: 1.1363x; 1.1041x over previous
#include <cuda_runtime.h>
#include <cuda_bf16.h>
#include <cstdint>

#define Bb 8
#define Ss 2048
#define Hh 3584
#define Ee 8
#define Rr 16
#define Kk 2
#define Jj 32
#define SCALING 2.0f

#define NSPLIT 8
#define HSPLIT (Hh / NSPLIT)     // 448
#define KC 16
#define NCH (HSPLIT / KC)        // 28 chunks per split
#define NTOK (Bb * Ss)           // 16384
#define LTOK 128                 // tokens per low CTA

// Scratch (static device globals — no allocation). 16B-aligned (float4 access).
__device__ __align__(16) float g_Ac [(size_t)Bb * Hh * Jj];          // [b][h][j], w*scaling folded
__device__ __align__(16) float g_Bc [(size_t)Bb * Jj * Hh];          // [b][j][h]
__device__ __align__(16) float g_lowp[(size_t)NSPLIT * NTOK * Jj];   // partials [split][tok][j]
__device__ __align__(16) float g_low [(size_t)NTOK * Jj];            // [tok][j]

union U2 { unsigned long long u; float2 f; };

__device__ __forceinline__ unsigned long long fma2(unsigned long long a,
                                                   unsigned long long b,
                                                   unsigned long long c) {
    unsigned long long d;
    asm("fma.rn.f32x2 %0, %1, %2, %3;" : "=l"(d) : "l"(a), "l"(b), "l"(c));
    return d;
}
__device__ __forceinline__ unsigned long long dup2(float v) {
    unsigned long long d;
    asm("mov.b64 %0, {%1, %1};" : "=l"(d) : "f"(v));
    return d;
}
__device__ __forceinline__ uint32_t smem_u32(const void* p) {
    uint32_t a;
    asm("{ .reg .u64 t; cvta.to.shared.u64 t, %1; cvt.u32.u64 %0, t; }"
        : "=r"(a) : "l"(p));
    return a;
}
__device__ __forceinline__ void cp16(uint32_t dst, const void* src) {
    asm volatile("cp.async.cg.shared.global [%0], [%1], 16;"
                 :: "r"(dst), "l"(src) : "memory");
}

// ---------------------------------------------------------------------------
// prep: Ac [b][h][j] (j-fast coalesced) and Bc [b][j][h] (float4-over-r reads).
// grid (Bb, Hh/128), 128 threads.
// ---------------------------------------------------------------------------
__global__ void __launch_bounds__(128) prep_kernel(const float* __restrict__ A,
                                                   const float* __restrict__ Bm,
                                                   const float* __restrict__ w,
                                                   const int*   __restrict__ idx)
{
    __shared__ int   es[Jj];
    __shared__ float scs[Jj];
    int b = blockIdx.x;
    int hb = blockIdx.y * 128;
    int tid = threadIdx.x;
    if (tid < Jj) {
        int k = tid >> 4;
        es[tid]  = idx[b * Kk + k];
        scs[tid] = w[b * Kk + k] * SCALING;
    }
    __syncthreads();

#pragma unroll 8
    for (int t = tid; t < 128 * Jj; t += 128) {
        int h = hb + (t >> 5);
        int j = t & 31;
        int r = j & 15;
        g_Ac[((size_t)b * Hh + h) * Jj + j] =
            A[((size_t)(es[j] * Rr + r)) * Hh + h] * scs[j];
    }
    // Bc: read float4 over contiguous r (4 j's per load), coalesced writes
#pragma unroll 8
    for (int t = tid; t < 128 * 8; t += 128) {
        int q = t >> 7;             // 0..7 : (k, r-quad)
        int h = hb + (t & 127);
        int k = q >> 2;
        int rq = q & 3;
        int e = es[k * 16];
        float4 v = *(const float4*)&Bm[((size_t)e * Hh + h) * Rr + rq * 4];
        size_t o = ((size_t)b * Jj + k * 16 + rq * 4) * Hh + h;
        g_Bc[o]          = v.x;
        g_Bc[o + Hh]     = v.y;
        g_Bc[o + 2 * Hh] = v.z;
        g_Bc[o + 3 * Hh] = v.w;
    }
}

// ---------------------------------------------------------------------------
// low v3: partial low over a k-split. grid (NTOK/128, NSPLIT), 128 threads.
// Thread = 4 tok x 8 j (jg = tid&3 -> j = jg*8..+7; sg = tid>>2, tokens
// sg + 32c). cp.async double-buffered tiles; 16 fma2 per kk per thread.
// Single wave: 1024 CTAs <= 148*7 resident.
// ---------------------------------------------------------------------------
__global__ void __launch_bounds__(128) low_kernel(const float* __restrict__ x)
{
    __shared__ __align__(16) float xsm[2][LTOK][20];   // [buf][tok][k]; row 80B
    __shared__ __align__(16) float asm_[2][KC][Jj];    // [buf][k][j]

    int tid = threadIdx.x;
    int jg = tid & 3;          // 4 j-groups of 8
    int sg = tid >> 2;         // 32 token-groups (stride-32 tokens)
    int tokbase = blockIdx.x * LTOK;
    int split = blockIdx.y;
    int b = tokbase >> 11;
    int k0base = split * HSPLIT;

    unsigned long long acc[4][4];   // [tok c][j-pair q]
#pragma unroll
    for (int c = 0; c < 4; c++)
#pragma unroll
        for (int q = 0; q < 4; q++) acc[c][q] = 0ULL;

    const float* xb = x + (size_t)tokbase * Hh + k0base;
    const float* acb = g_Ac + ((size_t)b * Hh + k0base) * Jj;

    uint32_t uxs = smem_u32(xsm);
    uint32_t uas = smem_u32(asm_);

    // load mappings
    int ltok = tid >> 2;            // +32i -> rows
    int lkq  = tid & 3;             // f4 within 16-k row

    // prologue: chunk 0 -> buf 0
#pragma unroll
    for (int i = 0; i < 4; i++) {
        int tok = ltok + 32 * i;
        cp16(uxs + (uint32_t)(tok * 80 + lkq * 16),
             xb + (size_t)tok * Hh + lkq * 4);
    }
    cp16(uas + (uint32_t)(tid * 16), acb + tid * 4);
    asm volatile("cp.async.commit_group;" ::: "memory");

    for (int g = 0; g < NCH; g++) {
        int cur = g & 1;
        __syncthreads();   // all threads done computing chunk g-1 (buf cur^1 free)
        if (g + 1 < NCH) {
            int nxt = cur ^ 1;
            uint32_t xoff = uxs + (uint32_t)(nxt * (LTOK * 20 * 4));
            uint32_t aoff = uas + (uint32_t)(nxt * (KC * Jj * 4));
            const float* xg = xb + (size_t)(g + 1) * KC;
            const float* ag = acb + (size_t)(g + 1) * KC * Jj;
#pragma unroll
            for (int i = 0; i < 4; i++) {
                int tok = ltok + 32 * i;
                cp16(xoff + (uint32_t)(tok * 80 + lkq * 16),
                     xg + (size_t)tok * Hh + lkq * 4);
            }
            cp16(aoff + (uint32_t)(tid * 16), ag + tid * 4);
            asm volatile("cp.async.commit_group;" ::: "memory");
            asm volatile("cp.async.wait_group 1;" ::: "memory");
        } else {
            asm volatile("cp.async.wait_group 0;" ::: "memory");
        }
        __syncthreads();   // chunk g visible to all

#pragma unroll
        for (int kk4 = 0; kk4 < KC / 4; kk4++) {
            float4 xq[4];
#pragma unroll
            for (int c = 0; c < 4; c++)
                xq[c] = *(const float4*)&xsm[cur][sg + 32 * c][kk4 * 4];
#pragma unroll
            for (int kl = 0; kl < 4; kl++) {
                int kk = kk4 * 4 + kl;
                ulonglong2 a0 = *(const ulonglong2*)&asm_[cur][kk][jg * 8];
                ulonglong2 a1 = *(const ulonglong2*)&asm_[cur][kk][jg * 8 + 4];
#pragma unroll
                for (int c = 0; c < 4; c++) {
                    float xv = (kl == 0) ? xq[c].x : (kl == 1) ? xq[c].y
                             : (kl == 2) ? xq[c].z : xq[c].w;
                    unsigned long long xd = dup2(xv);
                    acc[c][0] = fma2(xd, a0.x, acc[c][0]);
                    acc[c][1] = fma2(xd, a0.y, acc[c][1]);
                    acc[c][2] = fma2(xd, a1.x, acc[c][2]);
                    acc[c][3] = fma2(xd, a1.y, acc[c][3]);
                }
            }
        }
    }

    float* lp = g_lowp + (size_t)split * NTOK * Jj;
#pragma unroll
    for (int c = 0; c < 4; c++) {
        int tok = tokbase + sg + 32 * c;
#pragma unroll
        for (int q = 0; q < 4; q++) {
            U2 u; u.u = acc[c][q];
            *(float2*)&lp[(size_t)tok * Jj + jg * 8 + q * 2] = u.f;
        }
    }
}

// ---------------------------------------------------------------------------
// reduce: sum the NSPLIT partials. grid 256, 256 threads, 8 elems/thread.
// ---------------------------------------------------------------------------
__global__ void __launch_bounds__(256) reduce_kernel()
{
    int base = blockIdx.x * 2048;
#pragma unroll
    for (int r = 0; r < 8; r++) {
        int i = base + r * 256 + threadIdx.x;
        float v = 0.0f;
#pragma unroll
        for (int s = 0; s < NSPLIT; s++)
            v += g_lowp[(size_t)s * NTOK * Jj + i];
        g_low[i] = v;
    }
}

// ---------------------------------------------------------------------------
// out (R9-measured best, 92.1us): grid (NTOK/64, Hh/128), 128 threads.
// Thread = 4 h x 8 tokens per pass, 2 passes; launch_bounds(128,6).
// ---------------------------------------------------------------------------
#define HT 128
#define TT 64

__global__ void __launch_bounds__(128, 6) out_kernel(const float* __restrict__ base,
                                                     float* __restrict__ out)
{
    __shared__ __align__(16) float sB[Jj][HT];        // 16 KB
    __shared__ __align__(16) float sLowF[Jj][68];     // [j][tok]; 8.5 KB

    int tid = threadIdx.x;
    int h0 = blockIdx.y * HT;
    int tok0 = blockIdx.x * TT;
    int b = tok0 >> 11;

    const float* bc = g_Bc + (size_t)b * Jj * Hh + h0;
#pragma unroll
    for (int i = 0; i < 8; i++) {
        int f4 = tid + 128 * i;
        int j = f4 >> 5;
        int hq4 = f4 & 31;
        *(float4*)&sB[j][hq4 * 4] = *(const float4*)&bc[(size_t)j * Hh + hq4 * 4];
    }
#pragma unroll
    for (int i = 0; i < 4; i++) {
        int iv = tid + 128 * i;
        int j = iv & 31;
        int tg = iv >> 5;
        float4 v;
        v.x = g_low[(size_t)(tok0 + tg * 4 + 0) * Jj + j];
        v.y = g_low[(size_t)(tok0 + tg * 4 + 1) * Jj + j];
        v.z = g_low[(size_t)(tok0 + tg * 4 + 2) * Jj + j];
        v.w = g_low[(size_t)(tok0 + tg * 4 + 3) * Jj + j];
        *(float4*)&sLowF[j][tg * 4] = v;
    }
    __syncthreads();

    int hq = tid & 31;        // 32 h-groups of 4 -> 128 h
    int tg = tid >> 5;        // 4 token-groups of 16

#pragma unroll 1
    for (int p = 0; p < 2; p++) {
        int tl = tg * 16 + p * 8;
        unsigned long long acc[4][4];
#pragma unroll
        for (int q = 0; q < 4; q++)
#pragma unroll
            for (int hh = 0; hh < 4; hh++) acc[q][hh] = 0ULL;

#pragma unroll 4
        for (int j = 0; j < Jj; j++) {
            float4 bv = *(const float4*)&sB[j][hq * 4];
            unsigned long long d0 = dup2(bv.x), d1 = dup2(bv.y),
                               d2 = dup2(bv.z), d3 = dup2(bv.w);
#pragma unroll
            for (int m = 0; m < 2; m++) {
                ulonglong2 lq = *(const ulonglong2*)&sLowF[j][tl + m * 4];
                acc[2*m+0][0] = fma2(lq.x, d0, acc[2*m+0][0]);
                acc[2*m+0][1] = fma2(lq.x, d1, acc[2*m+0][1]);
                acc[2*m+0][2] = fma2(lq.x, d2, acc[2*m+0][2]);
                acc[2*m+0][3] = fma2(lq.x, d3, acc[2*m+0][3]);
                acc[2*m+1][0] = fma2(lq.y, d0, acc[2*m+1][0]);
                acc[2*m+1][1] = fma2(lq.y, d1, acc[2*m+1][1]);
                acc[2*m+1][2] = fma2(lq.y, d2, acc[2*m+1][2]);
                acc[2*m+1][3] = fma2(lq.y, d3, acc[2*m+1][3]);
            }
        }

#pragma unroll
        for (int t = 0; t < 8; t++) {
            int q = t >> 1;
            size_t gi = (size_t)(tok0 + tl + t) * Hh + h0 + hq * 4;
            float4 bs = *(const float4*)&base[gi];
            U2 a0, a1, a2, a3;
            a0.u = acc[q][0]; a1.u = acc[q][1]; a2.u = acc[q][2]; a3.u = acc[q][3];
            float4 o;
            if ((t & 1) == 0)
                o = make_float4(bs.x + a0.f.x, bs.y + a1.f.x,
                                bs.z + a2.f.x, bs.w + a3.f.x);
            else
                o = make_float4(bs.x + a0.f.y, bs.y + a1.f.y,
                                bs.z + a2.f.y, bs.w + a3.f.y);
            *(float4*)&out[gi] = o;
        }
    }
}

// ---------------------------------------------------------------------------
extern "C" void kernel_launch(void* const* d_in, const int* in_sizes, int n_in,
                              void* d_out, int out_size)
{
    const float* x    = (const float*)d_in[0];
    const float* base = (const float*)d_in[1];
    const float* lA   = (const float*)d_in[2];
    const float* lB   = (const float*)d_in[3];
    const float* w    = (const float*)d_in[4];
    const int*   idx  = (const int*)  d_in[5];
    float* out = (float*)d_out;

    prep_kernel<<<dim3(Bb, Hh / 128), 128>>>(lA, lB, w, idx);
    low_kernel<<<dim3(NTOK / LTOK, NSPLIT), 128>>>(x);
    reduce_kernel<<<256, 256>>>();
    out_kernel<<<dim3(NTOK / TT, Hh / HT), 128>>>(base, out);
}